// round 5
// baseline (speedup 1.0000x reference)
#include <cuda_runtime.h>

#define B_  2
#define S_  2048
#define D_  768
#define H_  12
#define HD_ 64
#define FF_ 3072
#define ROWS (B_ * S_)   // 4096

// ---------------- scratch (device globals; no allocation allowed) ----------
__device__ float gQ  [ROWS * D_];
__device__ float gK  [ROWS * D_];
__device__ float gV  [ROWS * D_];
__device__ float gCtx[ROWS * D_];
__device__ float gTmp[ROWS * D_];
__device__ float gX1 [ROWS * D_];
__device__ float gFF [ROWS * FF_];

// ---------------------------------------------------------------------------
// GEMM: C[m,n] = sum_k A[m,k] * B[n,k] + bias[n]   (NT, row-major A MxK, B NxK)
// BM=BN=128, BK=8, 256 threads, 8x8 per-thread microtile.
// All problem shapes here have M%128==0, N%128==0, K%8==0 -> no guards.
// ---------------------------------------------------------------------------
template <int RELU>
__global__ void __launch_bounds__(256)
gemm_nt_bias(const float* __restrict__ A, const float* __restrict__ Bm,
             const float* __restrict__ bias, float* __restrict__ C,
             int M, int N, int K)
{
    __shared__ float As[8][128];
    __shared__ float Bs[8][128];

    const int tid = threadIdx.x;
    const int bm = blockIdx.y * 128;
    const int bn = blockIdx.x * 128;
    const int tx = tid & 15;        // 0..15 -> N microtile
    const int ty = tid >> 4;        // 0..15 -> M microtile

    const int lrow = tid >> 1;          // 0..127
    const int lcol = (tid & 1) * 4;     // 0 or 4

    const float* Aptr = A  + (size_t)(bm + lrow) * K + lcol;
    const float* Bptr = Bm + (size_t)(bn + lrow) * K + lcol;

    float acc[8][8];
#pragma unroll
    for (int i = 0; i < 8; ++i)
#pragma unroll
        for (int j = 0; j < 8; ++j) acc[i][j] = 0.f;

    for (int k0 = 0; k0 < K; k0 += 8) {
        float4 a4 = *(const float4*)(Aptr + k0);
        float4 b4 = *(const float4*)(Bptr + k0);
        __syncthreads();                 // previous iteration's reads done
        As[lcol + 0][lrow] = a4.x;  As[lcol + 1][lrow] = a4.y;
        As[lcol + 2][lrow] = a4.z;  As[lcol + 3][lrow] = a4.w;
        Bs[lcol + 0][lrow] = b4.x;  Bs[lcol + 1][lrow] = b4.y;
        Bs[lcol + 2][lrow] = b4.z;  Bs[lcol + 3][lrow] = b4.w;
        __syncthreads();

#pragma unroll
        for (int kk = 0; kk < 8; ++kk) {
            float4 a0 = *(const float4*)&As[kk][ty * 8];
            float4 a1 = *(const float4*)&As[kk][ty * 8 + 4];
            float4 b0 = *(const float4*)&Bs[kk][tx * 8];
            float4 b1 = *(const float4*)&Bs[kk][tx * 8 + 4];
            float af[8] = {a0.x, a0.y, a0.z, a0.w, a1.x, a1.y, a1.z, a1.w};
            float bf[8] = {b0.x, b0.y, b0.z, b0.w, b1.x, b1.y, b1.z, b1.w};
#pragma unroll
            for (int i = 0; i < 8; ++i)
#pragma unroll
                for (int j = 0; j < 8; ++j)
                    acc[i][j] = fmaf(af[i], bf[j], acc[i][j]);
        }
    }

#pragma unroll
    for (int i = 0; i < 8; ++i) {
        float* crow = C + (size_t)(bm + ty * 8 + i) * N + bn + tx * 8;
#pragma unroll
        for (int j = 0; j < 8; ++j) {
            float v = acc[i][j] + bias[bn + tx * 8 + j];
            if (RELU) v = fmaxf(v, 0.f);
            crow[j] = v;
        }
    }
}

// ---------------------------------------------------------------------------
// Flash attention, fp32. One block = one (b,h, 64-row q-tile).
// 256 threads as 16x16; each thread owns a 4x4 tile of (q-rows x keys) and
// (q-rows x head-dims). Online softmax; ALiBi computed analytically from the
// slope (read exactly from alibi_bias[h,0,1]); causal by tile skip + diagonal
// masking with -1e30 (exp -> 0, identical to reference's -1e9 additive mask).
// ---------------------------------------------------------------------------
#define ATTN_SMEM_BYTES (4 * 64 * 68 * 4)

__global__ void __launch_bounds__(256)
attn_kernel(const float* __restrict__ Q, const float* __restrict__ K,
            const float* __restrict__ V, const float* __restrict__ alibi,
            float* __restrict__ O)
{
    extern __shared__ float smem[];
    float (*Qs)[68] = (float (*)[68])(smem);
    float (*Ks)[68] = (float (*)[68])(smem + 64 * 68);
    float (*Vs)[68] = (float (*)[68])(smem + 2 * 64 * 68);
    float (*Ps)[68] = (float (*)[68])(smem + 3 * 64 * 68);

    const int bh = blockIdx.y;
    const int b  = bh / H_;
    const int h  = bh % H_;
    const int q0 = blockIdx.x * 64;
    const float slope = alibi[(size_t)h * S_ * S_ + 1];  // slope * (1-0)
    const float scale = 0.125f;                          // 1/sqrt(64)

    const int tid = threadIdx.x;
    const int tx  = tid & 15;   // key / head-dim group
    const int ty  = tid >> 4;   // q-row group

    // load Q tile [64 x 64]
    const float* qbase = Q + (size_t)b * S_ * D_ + h * HD_;
    for (int i = tid; i < 64 * 16; i += 256) {
        int r = i >> 4, c = (i & 15) * 4;
        *(float4*)&Qs[r][c] = *(const float4*)(qbase + (size_t)(q0 + r) * D_ + c);
    }

    float m[4], l[4], acc[4][4];
#pragma unroll
    for (int i = 0; i < 4; ++i) {
        m[i] = -1e30f; l[i] = 0.f;
#pragma unroll
        for (int j = 0; j < 4; ++j) acc[i][j] = 0.f;
    }
    __syncthreads();

    const int ktiles = q0 / 64 + 1;   // causal: only tiles fully/partially <= diag
    for (int kt = 0; kt < ktiles; ++kt) {
        const int k0 = kt * 64;
        __syncthreads();              // prior tile's PV reads of Ps/Vs done
        const float* kbase = K + (size_t)(b * S_ + k0) * D_ + h * HD_;
        const float* vbase = V + (size_t)(b * S_ + k0) * D_ + h * HD_;
        for (int i = tid; i < 64 * 16; i += 256) {
            int r = i >> 4, c = (i & 15) * 4;
            *(float4*)&Ks[r][c] = *(const float4*)(kbase + (size_t)r * D_ + c);
            *(float4*)&Vs[r][c] = *(const float4*)(vbase + (size_t)r * D_ + c);
        }
        __syncthreads();

        // scores s[4][4] = Q(ty*4+ii) . K(tx*4+jj)
        float s[4][4];
#pragma unroll
        for (int i = 0; i < 4; ++i)
#pragma unroll
            for (int j = 0; j < 4; ++j) s[i][j] = 0.f;

        for (int d = 0; d < 64; d += 4) {
            float4 q4[4], k4[4];
#pragma unroll
            for (int i = 0; i < 4; ++i) q4[i] = *(const float4*)&Qs[ty * 4 + i][d];
#pragma unroll
            for (int j = 0; j < 4; ++j) k4[j] = *(const float4*)&Ks[tx * 4 + j][d];
#pragma unroll
            for (int i = 0; i < 4; ++i)
#pragma unroll
                for (int j = 0; j < 4; ++j) {
                    s[i][j] = fmaf(q4[i].x, k4[j].x, s[i][j]);
                    s[i][j] = fmaf(q4[i].y, k4[j].y, s[i][j]);
                    s[i][j] = fmaf(q4[i].z, k4[j].z, s[i][j]);
                    s[i][j] = fmaf(q4[i].w, k4[j].w, s[i][j]);
                }
        }

        // scale + alibi + causal mask, online softmax update
#pragma unroll
        for (int i = 0; i < 4; ++i) {
            const int gi = q0 + ty * 4 + i;
#pragma unroll
            for (int j = 0; j < 4; ++j) {
                const int gj = k0 + tx * 4 + j;
                float v = s[i][j] * scale + slope * (float)(gj - gi);
                if (gj > gi) v = -1e30f;
                s[i][j] = v;
            }
            float rm = fmaxf(fmaxf(s[i][0], s[i][1]), fmaxf(s[i][2], s[i][3]));
#pragma unroll
            for (int o = 1; o < 16; o <<= 1)
                rm = fmaxf(rm, __shfl_xor_sync(0xffffffffu, rm, o, 16));

            const float mnew = fmaxf(m[i], rm);
            const float corr = __expf(m[i] - mnew);
            float rowsum = 0.f;
#pragma unroll
            for (int j = 0; j < 4; ++j) {
                float p = __expf(s[i][j] - mnew);
                Ps[ty * 4 + i][tx * 4 + j] = p;
                rowsum += p;
            }
#pragma unroll
            for (int o = 1; o < 16; o <<= 1)
                rowsum += __shfl_xor_sync(0xffffffffu, rowsum, o, 16);

            l[i] = l[i] * corr + rowsum;
            m[i] = mnew;
#pragma unroll
            for (int j = 0; j < 4; ++j) acc[i][j] *= corr;
        }
        __syncthreads();   // Ps visible to all

        // acc += P @ V   (keys 0..63)
        for (int kk = 0; kk < 64; ++kk) {
            float4 v4 = *(const float4*)&Vs[kk][tx * 4];
#pragma unroll
            for (int i = 0; i < 4; ++i) {
                float p = Ps[ty * 4 + i][kk];
                acc[i][0] = fmaf(p, v4.x, acc[i][0]);
                acc[i][1] = fmaf(p, v4.y, acc[i][1]);
                acc[i][2] = fmaf(p, v4.z, acc[i][2]);
                acc[i][3] = fmaf(p, v4.w, acc[i][3]);
            }
        }
    }

    // write context in (b, s, h, hd) layout = (4096, 768)
#pragma unroll
    for (int i = 0; i < 4; ++i) {
        const float inv = 1.f / l[i];
        float* orow = O + (size_t)(b * S_ + q0 + ty * 4 + i) * D_ + h * HD_ + tx * 4;
#pragma unroll
        for (int j = 0; j < 4; ++j) orow[j] = acc[i][j] * inv;
    }
}

// ---------------------------------------------------------------------------
// out = LayerNorm(A_row + B_row) * g + beta ;  row length 768, 256 threads.
// ---------------------------------------------------------------------------
__global__ void __launch_bounds__(256)
add_ln_kernel(const float* __restrict__ A, const float* __restrict__ Bm,
              const float* __restrict__ g, const float* __restrict__ beta,
              float* __restrict__ out)
{
    const int row = blockIdx.x;
    const int tid = threadIdx.x;
    const float* a = A  + (size_t)row * D_;
    const float* b = Bm + (size_t)row * D_;

    float v[3], s = 0.f, ss = 0.f;
#pragma unroll
    for (int i = 0; i < 3; ++i) {
        int c = tid + i * 256;
        v[i] = a[c] + b[c];
        s  += v[i];
        ss += v[i] * v[i];
    }
#pragma unroll
    for (int o = 16; o > 0; o >>= 1) {
        s  += __shfl_xor_sync(0xffffffffu, s,  o);
        ss += __shfl_xor_sync(0xffffffffu, ss, o);
    }
    __shared__ float shs[8], shss[8];
    if ((tid & 31) == 0) { shs[tid >> 5] = s; shss[tid >> 5] = ss; }
    __syncthreads();
    __shared__ float sh_mean, sh_inv;
    if (tid == 0) {
        float ts = 0.f, tss = 0.f;
#pragma unroll
        for (int w = 0; w < 8; ++w) { ts += shs[w]; tss += shss[w]; }
        float mean = ts * (1.f / D_);
        float var  = tss * (1.f / D_) - mean * mean;
        sh_mean = mean;
        sh_inv  = rsqrtf(var + 1e-5f);
    }
    __syncthreads();
    const float mean = sh_mean, inv = sh_inv;
    float* o = out + (size_t)row * D_;
#pragma unroll
    for (int i = 0; i < 3; ++i) {
        int c = tid + i * 256;
        o[c] = (v[i] - mean) * inv * g[c] + beta[c];
    }
}

// ---------------------------------------------------------------------------
static void* sym_addr(const void* symbol) {
    void* p = nullptr;
    cudaGetSymbolAddress(&p, symbol);
    return p;
}

extern "C" void kernel_launch(void* const* d_in, const int* in_sizes, int n_in,
                              void* d_out, int out_size)
{
    const float* x     = (const float*)d_in[0];
    // d_in[1] = mask (unused: causal handled analytically)
    const float* alibi = (const float*)d_in[2];
    const float* wq = (const float*)d_in[3];
    const float* bq = (const float*)d_in[4];
    const float* wk = (const float*)d_in[5];
    const float* bk = (const float*)d_in[6];
    const float* wv = (const float*)d_in[7];
    const float* bv = (const float*)d_in[8];
    const float* wo = (const float*)d_in[9];
    const float* bo = (const float*)d_in[10];
    const float* w1 = (const float*)d_in[11];
    const float* b1 = (const float*)d_in[12];
    const float* w2 = (const float*)d_in[13];
    const float* b2 = (const float*)d_in[14];
    const float* g1 = (const float*)d_in[15];
    const float* be1= (const float*)d_in[16];
    const float* g2 = (const float*)d_in[17];
    const float* be2= (const float*)d_in[18];
    float* out = (float*)d_out;

    float* q   = (float*)sym_addr(gQ);
    float* k   = (float*)sym_addr(gK);
    float* v   = (float*)sym_addr(gV);
    float* ctx = (float*)sym_addr(gCtx);
    float* tmp = (float*)sym_addr(gTmp);
    float* x1  = (float*)sym_addr(gX1);
    float* ff  = (float*)sym_addr(gFF);

    cudaFuncSetAttribute(attn_kernel,
                         cudaFuncAttributeMaxDynamicSharedMemorySize,
                         ATTN_SMEM_BYTES);

    // QKV projections: (4096 x 768) x (768 x 768)^T
    dim3 gproj(D_ / 128, ROWS / 128);
    gemm_nt_bias<0><<<gproj, 256>>>(x, wq, bq, q, ROWS, D_, D_);
    gemm_nt_bias<0><<<gproj, 256>>>(x, wk, bk, k, ROWS, D_, D_);
    gemm_nt_bias<0><<<gproj, 256>>>(x, wv, bv, v, ROWS, D_, D_);

    // attention
    dim3 gattn(S_ / 64, B_ * H_);
    attn_kernel<<<gattn, 256, ATTN_SMEM_BYTES>>>(q, k, v, alibi, ctx);

    // output projection, residual + LN1
    gemm_nt_bias<0><<<gproj, 256>>>(ctx, wo, bo, tmp, ROWS, D_, D_);
    add_ln_kernel<<<ROWS, 256>>>(x, tmp, g1, be1, x1);

    // FFN
    dim3 gff1(FF_ / 128, ROWS / 128);
    gemm_nt_bias<1><<<gff1, 256>>>(x1, w1, b1, ff, ROWS, FF_, D_);
    gemm_nt_bias<0><<<gproj, 256>>>(ff, w2, b2, tmp, ROWS, D_, FF_);

    // residual + LN2 -> output
    add_ln_kernel<<<ROWS, 256>>>(x1, tmp, g2, be2, out);
}

// round 7
// speedup vs baseline: 1.7173x; 1.7173x over previous
#include <cuda_runtime.h>
#include <cstdint>

#define B_  2
#define S_  2048
#define D_  768
#define H_  12
#define HD_ 64
#define FF_ 3072
#define ROWS (B_ * S_)   // 4096

// ---------------- scratch (device globals; no allocation allowed) ----------
__device__ float gQ  [ROWS * D_];
__device__ float gK  [ROWS * D_];
__device__ float gV  [ROWS * D_];
__device__ float gCtx[ROWS * D_];
__device__ float gTmp[ROWS * D_];
__device__ float gX1 [ROWS * D_];
__device__ float gFF [ROWS * FF_];

// ---------------------------------------------------------------------------
// tf32 tensor-core GEMM (NT): C[m,n] = sum_k A[m,k]*B[n,k] + bias[n]
// Block 128x128xBK16, 256 threads = 8 warps in 2(M) x 4(N), warp tile 64x32.
// mma.sync m16n8k8 tf32, fp32 accum. XOR-swizzled smem -> conflict-free LDS.
// Shapes here: M%128==0, N%128==0, K%16==0.
// ---------------------------------------------------------------------------
__device__ __forceinline__ uint32_t f2tf32(float x) {
    uint32_t u;
    asm("cvt.rna.tf32.f32 %0, %1;" : "=r"(u) : "f"(x));
    return u;
}

__device__ __forceinline__ void mma_tf32(float* c, const uint32_t* a, const uint32_t* b) {
    asm volatile(
        "mma.sync.aligned.m16n8k8.row.col.f32.tf32.tf32.f32 "
        "{%0,%1,%2,%3}, {%4,%5,%6,%7}, {%8,%9}, {%0,%1,%2,%3};"
        : "+f"(c[0]), "+f"(c[1]), "+f"(c[2]), "+f"(c[3])
        : "r"(a[0]), "r"(a[1]), "r"(a[2]), "r"(a[3]), "r"(b[0]), "r"(b[1]));
}

// swizzled index into a [128][16] tile: spreads k across banks per row pair
__device__ __forceinline__ int swz(int r, int c) {
    return r * 16 + (c ^ (((r >> 1) & 3) << 2));
}

template <int RELU>
__global__ void __launch_bounds__(256)
gemm_tf32(const float* __restrict__ A, const float* __restrict__ Bm,
          const float* __restrict__ bias, float* __restrict__ C,
          int N, int K)
{
    __shared__ uint32_t As[128 * 16];
    __shared__ uint32_t Bs[128 * 16];

    const int tid  = threadIdx.x;
    const int lane = tid & 31;
    const int warp = tid >> 5;
    const int bm = blockIdx.y * 128;
    const int bn = blockIdx.x * 128;

    const int m_base = (warp >> 2) * 64;   // 0 or 64
    const int n_base = (warp & 3) * 32;    // 0,32,64,96

    // loader: thread covers rows lr and lr+64, 4 consecutive floats at col lc
    const int lr = tid >> 2;            // 0..63
    const int lc = (tid & 3) * 4;       // 0,4,8,12

    const float* Ap0 = A  + (size_t)(bm + lr)      * K + lc;
    const float* Ap1 = A  + (size_t)(bm + lr + 64) * K + lc;
    const float* Bp0 = Bm + (size_t)(bn + lr)      * K + lc;
    const float* Bp1 = Bm + (size_t)(bn + lr + 64) * K + lc;

    const int st0 = swz(lr,      lc);   // float4-aligned (swizzle is mult of 4)
    const int st1 = swz(lr + 64, lc);

    float acc[4][4][4];
#pragma unroll
    for (int mi = 0; mi < 4; ++mi)
#pragma unroll
        for (int ni = 0; ni < 4; ++ni)
#pragma unroll
            for (int r = 0; r < 4; ++r) acc[mi][ni][r] = 0.f;

    float4 a0g = *(const float4*)Ap0;
    float4 a1g = *(const float4*)Ap1;
    float4 b0g = *(const float4*)Bp0;
    float4 b1g = *(const float4*)Bp1;

    for (int k0 = 0; k0 < K; k0 += 16) {
        __syncthreads();                    // prior compute done reading smem
        As[st0 + 0] = f2tf32(a0g.x); As[st0 + 1] = f2tf32(a0g.y);
        As[st0 + 2] = f2tf32(a0g.z); As[st0 + 3] = f2tf32(a0g.w);
        As[st1 + 0] = f2tf32(a1g.x); As[st1 + 1] = f2tf32(a1g.y);
        As[st1 + 2] = f2tf32(a1g.z); As[st1 + 3] = f2tf32(a1g.w);
        Bs[st0 + 0] = f2tf32(b0g.x); Bs[st0 + 1] = f2tf32(b0g.y);
        Bs[st0 + 2] = f2tf32(b0g.z); Bs[st0 + 3] = f2tf32(b0g.w);
        Bs[st1 + 0] = f2tf32(b1g.x); Bs[st1 + 1] = f2tf32(b1g.y);
        Bs[st1 + 2] = f2tf32(b1g.z); Bs[st1 + 3] = f2tf32(b1g.w);
        __syncthreads();

        if (k0 + 16 < K) {                  // prefetch next tile under compute
            a0g = *(const float4*)(Ap0 + k0 + 16);
            a1g = *(const float4*)(Ap1 + k0 + 16);
            b0g = *(const float4*)(Bp0 + k0 + 16);
            b1g = *(const float4*)(Bp1 + k0 + 16);
        }

#pragma unroll
        for (int ks = 0; ks < 2; ++ks) {
            const int kk = ks * 8 + (lane & 3);
            uint32_t a[4][4], b[4][2];
#pragma unroll
            for (int mi = 0; mi < 4; ++mi) {
                const int r0 = m_base + mi * 16 + (lane >> 2);
                const int r1 = r0 + 8;
                a[mi][0] = As[swz(r0, kk)];
                a[mi][1] = As[swz(r1, kk)];
                a[mi][2] = As[swz(r0, kk + 4)];
                a[mi][3] = As[swz(r1, kk + 4)];
            }
#pragma unroll
            for (int ni = 0; ni < 4; ++ni) {
                const int nn = n_base + ni * 8 + (lane >> 2);
                b[ni][0] = Bs[swz(nn, kk)];
                b[ni][1] = Bs[swz(nn, kk + 4)];
            }
#pragma unroll
            for (int mi = 0; mi < 4; ++mi)
#pragma unroll
                for (int ni = 0; ni < 4; ++ni)
                    mma_tf32(acc[mi][ni], a[mi], b[ni]);
        }
    }

    // epilogue: c0:(gr,gc) c1:(gr,gc+1) c2:(gr+8,gc) c3:(gr+8,gc+1)
    const int gr = lane >> 2;
    const int gc = (lane & 3) * 2;
#pragma unroll
    for (int ni = 0; ni < 4; ++ni) {
        const int n0 = bn + n_base + ni * 8 + gc;
        const float bv0 = bias[n0], bv1 = bias[n0 + 1];
#pragma unroll
        for (int mi = 0; mi < 4; ++mi) {
            const int row = bm + m_base + mi * 16 + gr;
            float2 v0 = make_float2(acc[mi][ni][0] + bv0, acc[mi][ni][1] + bv1);
            float2 v1 = make_float2(acc[mi][ni][2] + bv0, acc[mi][ni][3] + bv1);
            if (RELU) {
                v0.x = fmaxf(v0.x, 0.f); v0.y = fmaxf(v0.y, 0.f);
                v1.x = fmaxf(v1.x, 0.f); v1.y = fmaxf(v1.y, 0.f);
            }
            *(float2*)&C[(size_t)row * N + n0]       = v0;
            *(float2*)&C[(size_t)(row + 8) * N + n0] = v1;
        }
    }
}

// ---------------------------------------------------------------------------
// Flash attention, fp32 (unchanged from R1 — correct, 785us; next target).
// ---------------------------------------------------------------------------
#define ATTN_SMEM_BYTES (4 * 64 * 68 * 4)

__global__ void __launch_bounds__(256)
attn_kernel(const float* __restrict__ Q, const float* __restrict__ K,
            const float* __restrict__ V, const float* __restrict__ alibi,
            float* __restrict__ O)
{
    extern __shared__ float smem[];
    float (*Qs)[68] = (float (*)[68])(smem);
    float (*Ks)[68] = (float (*)[68])(smem + 64 * 68);
    float (*Vs)[68] = (float (*)[68])(smem + 2 * 64 * 68);
    float (*Ps)[68] = (float (*)[68])(smem + 3 * 64 * 68);

    const int bh = blockIdx.y;
    const int b  = bh / H_;
    const int h  = bh % H_;
    const int q0 = blockIdx.x * 64;
    const float slope = alibi[(size_t)h * S_ * S_ + 1];  // slope * (1-0)
    const float scale = 0.125f;                          // 1/sqrt(64)

    const int tid = threadIdx.x;
    const int tx  = tid & 15;
    const int ty  = tid >> 4;

    const float* qbase = Q + (size_t)b * S_ * D_ + h * HD_;
    for (int i = tid; i < 64 * 16; i += 256) {
        int r = i >> 4, c = (i & 15) * 4;
        *(float4*)&Qs[r][c] = *(const float4*)(qbase + (size_t)(q0 + r) * D_ + c);
    }

    float m[4], l[4], acc[4][4];
#pragma unroll
    for (int i = 0; i < 4; ++i) {
        m[i] = -1e30f; l[i] = 0.f;
#pragma unroll
        for (int j = 0; j < 4; ++j) acc[i][j] = 0.f;
    }
    __syncthreads();

    const int ktiles = q0 / 64 + 1;
    for (int kt = 0; kt < ktiles; ++kt) {
        const int k0 = kt * 64;
        __syncthreads();
        const float* kbase = K + (size_t)(b * S_ + k0) * D_ + h * HD_;
        const float* vbase = V + (size_t)(b * S_ + k0) * D_ + h * HD_;
        for (int i = tid; i < 64 * 16; i += 256) {
            int r = i >> 4, c = (i & 15) * 4;
            *(float4*)&Ks[r][c] = *(const float4*)(kbase + (size_t)r * D_ + c);
            *(float4*)&Vs[r][c] = *(const float4*)(vbase + (size_t)r * D_ + c);
        }
        __syncthreads();

        float s[4][4];
#pragma unroll
        for (int i = 0; i < 4; ++i)
#pragma unroll
            for (int j = 0; j < 4; ++j) s[i][j] = 0.f;

        for (int d = 0; d < 64; d += 4) {
            float4 q4[4], k4[4];
#pragma unroll
            for (int i = 0; i < 4; ++i) q4[i] = *(const float4*)&Qs[ty * 4 + i][d];
#pragma unroll
            for (int j = 0; j < 4; ++j) k4[j] = *(const float4*)&Ks[tx * 4 + j][d];
#pragma unroll
            for (int i = 0; i < 4; ++i)
#pragma unroll
                for (int j = 0; j < 4; ++j) {
                    s[i][j] = fmaf(q4[i].x, k4[j].x, s[i][j]);
                    s[i][j] = fmaf(q4[i].y, k4[j].y, s[i][j]);
                    s[i][j] = fmaf(q4[i].z, k4[j].z, s[i][j]);
                    s[i][j] = fmaf(q4[i].w, k4[j].w, s[i][j]);
                }
        }

#pragma unroll
        for (int i = 0; i < 4; ++i) {
            const int gi = q0 + ty * 4 + i;
#pragma unroll
            for (int j = 0; j < 4; ++j) {
                const int gj = k0 + tx * 4 + j;
                float v = s[i][j] * scale + slope * (float)(gj - gi);
                if (gj > gi) v = -1e30f;
                s[i][j] = v;
            }
            float rm = fmaxf(fmaxf(s[i][0], s[i][1]), fmaxf(s[i][2], s[i][3]));
#pragma unroll
            for (int o = 1; o < 16; o <<= 1)
                rm = fmaxf(rm, __shfl_xor_sync(0xffffffffu, rm, o, 16));

            const float mnew = fmaxf(m[i], rm);
            const float corr = __expf(m[i] - mnew);
            float rowsum = 0.f;
#pragma unroll
            for (int j = 0; j < 4; ++j) {
                float p = __expf(s[i][j] - mnew);
                Ps[ty * 4 + i][tx * 4 + j] = p;
                rowsum += p;
            }
#pragma unroll
            for (int o = 1; o < 16; o <<= 1)
                rowsum += __shfl_xor_sync(0xffffffffu, rowsum, o, 16);

            l[i] = l[i] * corr + rowsum;
            m[i] = mnew;
#pragma unroll
            for (int j = 0; j < 4; ++j) acc[i][j] *= corr;
        }
        __syncthreads();

        for (int kk = 0; kk < 64; ++kk) {
            float4 v4 = *(const float4*)&Vs[kk][tx * 4];
#pragma unroll
            for (int i = 0; i < 4; ++i) {
                float p = Ps[ty * 4 + i][kk];
                acc[i][0] = fmaf(p, v4.x, acc[i][0]);
                acc[i][1] = fmaf(p, v4.y, acc[i][1]);
                acc[i][2] = fmaf(p, v4.z, acc[i][2]);
                acc[i][3] = fmaf(p, v4.w, acc[i][3]);
            }
        }
    }

#pragma unroll
    for (int i = 0; i < 4; ++i) {
        const float inv = 1.f / l[i];
        float* orow = O + (size_t)(b * S_ + q0 + ty * 4 + i) * D_ + h * HD_ + tx * 4;
#pragma unroll
        for (int j = 0; j < 4; ++j) orow[j] = acc[i][j] * inv;
    }
}

// ---------------------------------------------------------------------------
// out = LayerNorm(A_row + B_row) * g + beta ;  row length 768, 256 threads.
// ---------------------------------------------------------------------------
__global__ void __launch_bounds__(256)
add_ln_kernel(const float* __restrict__ A, const float* __restrict__ Bm,
              const float* __restrict__ g, const float* __restrict__ beta,
              float* __restrict__ out)
{
    const int row = blockIdx.x;
    const int tid = threadIdx.x;
    const float* a = A  + (size_t)row * D_;
    const float* b = Bm + (size_t)row * D_;

    float v[3], s = 0.f, ss = 0.f;
#pragma unroll
    for (int i = 0; i < 3; ++i) {
        int c = tid + i * 256;
        v[i] = a[c] + b[c];
        s  += v[i];
        ss += v[i] * v[i];
    }
#pragma unroll
    for (int o = 16; o > 0; o >>= 1) {
        s  += __shfl_xor_sync(0xffffffffu, s,  o);
        ss += __shfl_xor_sync(0xffffffffu, ss, o);
    }
    __shared__ float shs[8], shss[8];
    if ((tid & 31) == 0) { shs[tid >> 5] = s; shss[tid >> 5] = ss; }
    __syncthreads();
    __shared__ float sh_mean, sh_inv;
    if (tid == 0) {
        float ts = 0.f, tss = 0.f;
#pragma unroll
        for (int w = 0; w < 8; ++w) { ts += shs[w]; tss += shss[w]; }
        float mean = ts * (1.f / D_);
        float var  = tss * (1.f / D_) - mean * mean;
        sh_mean = mean;
        sh_inv  = rsqrtf(var + 1e-5f);
    }
    __syncthreads();
    const float mean = sh_mean, inv = sh_inv;
    float* o = out + (size_t)row * D_;
#pragma unroll
    for (int i = 0; i < 3; ++i) {
        int c = tid + i * 256;
        o[c] = (v[i] - mean) * inv * g[c] + beta[c];
    }
}

// ---------------------------------------------------------------------------
static void* sym_addr(const void* symbol) {
    void* p = nullptr;
    cudaGetSymbolAddress(&p, symbol);
    return p;
}

extern "C" void kernel_launch(void* const* d_in, const int* in_sizes, int n_in,
                              void* d_out, int out_size)
{
    const float* x     = (const float*)d_in[0];
    // d_in[1] = mask (unused: causal handled analytically)
    const float* alibi = (const float*)d_in[2];
    const float* wq = (const float*)d_in[3];
    const float* bq = (const float*)d_in[4];
    const float* wk = (const float*)d_in[5];
    const float* bk = (const float*)d_in[6];
    const float* wv = (const float*)d_in[7];
    const float* bv = (const float*)d_in[8];
    const float* wo = (const float*)d_in[9];
    const float* bo = (const float*)d_in[10];
    const float* w1 = (const float*)d_in[11];
    const float* b1 = (const float*)d_in[12];
    const float* w2 = (const float*)d_in[13];
    const float* b2 = (const float*)d_in[14];
    const float* g1 = (const float*)d_in[15];
    const float* be1= (const float*)d_in[16];
    const float* g2 = (const float*)d_in[17];
    const float* be2= (const float*)d_in[18];
    float* out = (float*)d_out;

    float* q   = (float*)sym_addr(gQ);
    float* k   = (float*)sym_addr(gK);
    float* v   = (float*)sym_addr(gV);
    float* ctx = (float*)sym_addr(gCtx);
    float* tmp = (float*)sym_addr(gTmp);
    float* x1  = (float*)sym_addr(gX1);
    float* ff  = (float*)sym_addr(gFF);

    cudaFuncSetAttribute(attn_kernel,
                         cudaFuncAttributeMaxDynamicSharedMemorySize,
                         ATTN_SMEM_BYTES);

    // QKV projections: (4096 x 768) x (768 x 768)^T   [tf32 tensor cores]
    dim3 gproj(D_ / 128, ROWS / 128);
    gemm_tf32<0><<<gproj, 256>>>(x, wq, bq, q, D_, D_);
    gemm_tf32<0><<<gproj, 256>>>(x, wk, bk, k, D_, D_);
    gemm_tf32<0><<<gproj, 256>>>(x, wv, bv, v, D_, D_);

    // attention (fp32)
    dim3 gattn(S_ / 64, B_ * H_);
    attn_kernel<<<gattn, 256, ATTN_SMEM_BYTES>>>(q, k, v, alibi, ctx);

    // output projection, residual + LN1
    gemm_tf32<0><<<gproj, 256>>>(ctx, wo, bo, tmp, D_, D_);
    add_ln_kernel<<<ROWS, 256>>>(x, tmp, g1, be1, x1);

    // FFN
    dim3 gff1(FF_ / 128, ROWS / 128);
    gemm_tf32<1><<<gff1, 256>>>(x1, w1, b1, ff, FF_, D_);
    gemm_tf32<0><<<gproj, 256>>>(ff, w2, b2, tmp, D_, FF_);

    // residual + LN2 -> output
    add_ln_kernel<<<ROWS, 256>>>(x1, tmp, g2, be2, out);
}

// round 8
// speedup vs baseline: 2.8559x; 1.6631x over previous
#include <cuda_runtime.h>
#include <cstdint>

#define B_  2
#define S_  2048
#define D_  768
#define H_  12
#define HD_ 64
#define FF_ 3072
#define ROWS (B_ * S_)   // 4096

// ---------------- scratch (device globals; no allocation allowed) ----------
__device__ float gQ  [ROWS * D_];
__device__ float gK  [ROWS * D_];
__device__ float gV  [ROWS * D_];
__device__ float gCtx[ROWS * D_];
__device__ float gTmp[ROWS * D_];
__device__ float gX1 [ROWS * D_];
__device__ float gFF [ROWS * FF_];

// ---------------------------------------------------------------------------
__device__ __forceinline__ uint32_t f2tf32(float x) {
    uint32_t u;
    asm("cvt.rna.tf32.f32 %0, %1;" : "=r"(u) : "f"(x));
    return u;
}

__device__ __forceinline__ void mma_tf32(float* c, const uint32_t* a, const uint32_t* b) {
    asm volatile(
        "mma.sync.aligned.m16n8k8.row.col.f32.tf32.tf32.f32 "
        "{%0,%1,%2,%3}, {%4,%5,%6,%7}, {%8,%9}, {%0,%1,%2,%3};"
        : "+f"(c[0]), "+f"(c[1]), "+f"(c[2]), "+f"(c[3])
        : "r"(a[0]), "r"(a[1]), "r"(a[2]), "r"(a[3]), "r"(b[0]), "r"(b[1]));
}

// ---------------------------------------------------------------------------
// tf32 tensor-core GEMM (NT) — unchanged from R5 (validated, ~78 TF/s).
// ---------------------------------------------------------------------------
__device__ __forceinline__ int swz(int r, int c) {
    return r * 16 + (c ^ (((r >> 1) & 3) << 2));
}

template <int RELU>
__global__ void __launch_bounds__(256)
gemm_tf32(const float* __restrict__ A, const float* __restrict__ Bm,
          const float* __restrict__ bias, float* __restrict__ C,
          int N, int K)
{
    __shared__ uint32_t As[128 * 16];
    __shared__ uint32_t Bs[128 * 16];

    const int tid  = threadIdx.x;
    const int lane = tid & 31;
    const int warp = tid >> 5;
    const int bm = blockIdx.y * 128;
    const int bn = blockIdx.x * 128;

    const int m_base = (warp >> 2) * 64;
    const int n_base = (warp & 3) * 32;

    const int lr = tid >> 2;
    const int lc = (tid & 3) * 4;

    const float* Ap0 = A  + (size_t)(bm + lr)      * K + lc;
    const float* Ap1 = A  + (size_t)(bm + lr + 64) * K + lc;
    const float* Bp0 = Bm + (size_t)(bn + lr)      * K + lc;
    const float* Bp1 = Bm + (size_t)(bn + lr + 64) * K + lc;

    const int st0 = swz(lr,      lc);
    const int st1 = swz(lr + 64, lc);

    float acc[4][4][4];
#pragma unroll
    for (int mi = 0; mi < 4; ++mi)
#pragma unroll
        for (int ni = 0; ni < 4; ++ni)
#pragma unroll
            for (int r = 0; r < 4; ++r) acc[mi][ni][r] = 0.f;

    float4 a0g = *(const float4*)Ap0;
    float4 a1g = *(const float4*)Ap1;
    float4 b0g = *(const float4*)Bp0;
    float4 b1g = *(const float4*)Bp1;

    for (int k0 = 0; k0 < K; k0 += 16) {
        __syncthreads();
        As[st0 + 0] = f2tf32(a0g.x); As[st0 + 1] = f2tf32(a0g.y);
        As[st0 + 2] = f2tf32(a0g.z); As[st0 + 3] = f2tf32(a0g.w);
        As[st1 + 0] = f2tf32(a1g.x); As[st1 + 1] = f2tf32(a1g.y);
        As[st1 + 2] = f2tf32(a1g.z); As[st1 + 3] = f2tf32(a1g.w);
        Bs[st0 + 0] = f2tf32(b0g.x); Bs[st0 + 1] = f2tf32(b0g.y);
        Bs[st0 + 2] = f2tf32(b0g.z); Bs[st0 + 3] = f2tf32(b0g.w);
        Bs[st1 + 0] = f2tf32(b1g.x); Bs[st1 + 1] = f2tf32(b1g.y);
        Bs[st1 + 2] = f2tf32(b1g.z); Bs[st1 + 3] = f2tf32(b1g.w);
        __syncthreads();

        if (k0 + 16 < K) {
            a0g = *(const float4*)(Ap0 + k0 + 16);
            a1g = *(const float4*)(Ap1 + k0 + 16);
            b0g = *(const float4*)(Bp0 + k0 + 16);
            b1g = *(const float4*)(Bp1 + k0 + 16);
        }

#pragma unroll
        for (int ks = 0; ks < 2; ++ks) {
            const int kk = ks * 8 + (lane & 3);
            uint32_t a[4][4], b[4][2];
#pragma unroll
            for (int mi = 0; mi < 4; ++mi) {
                const int r0 = m_base + mi * 16 + (lane >> 2);
                const int r1 = r0 + 8;
                a[mi][0] = As[swz(r0, kk)];
                a[mi][1] = As[swz(r1, kk)];
                a[mi][2] = As[swz(r0, kk + 4)];
                a[mi][3] = As[swz(r1, kk + 4)];
            }
#pragma unroll
            for (int ni = 0; ni < 4; ++ni) {
                const int nn = n_base + ni * 8 + (lane >> 2);
                b[ni][0] = Bs[swz(nn, kk)];
                b[ni][1] = Bs[swz(nn, kk + 4)];
            }
#pragma unroll
            for (int mi = 0; mi < 4; ++mi)
#pragma unroll
                for (int ni = 0; ni < 4; ++ni)
                    mma_tf32(acc[mi][ni], a[mi], b[ni]);
        }
    }

    const int gr = lane >> 2;
    const int gc = (lane & 3) * 2;
#pragma unroll
    for (int ni = 0; ni < 4; ++ni) {
        const int n0 = bn + n_base + ni * 8 + gc;
        const float bv0 = bias[n0], bv1 = bias[n0 + 1];
#pragma unroll
        for (int mi = 0; mi < 4; ++mi) {
            const int row = bm + m_base + mi * 16 + gr;
            float2 v0 = make_float2(acc[mi][ni][0] + bv0, acc[mi][ni][1] + bv1);
            float2 v1 = make_float2(acc[mi][ni][2] + bv0, acc[mi][ni][3] + bv1);
            if (RELU) {
                v0.x = fmaxf(v0.x, 0.f); v0.y = fmaxf(v0.y, 0.f);
                v1.x = fmaxf(v1.x, 0.f); v1.y = fmaxf(v1.y, 0.f);
            }
            *(float2*)&C[(size_t)row * N + n0]       = v0;
            *(float2*)&C[(size_t)(row + 8) * N + n0] = v1;
        }
    }
}

// ---------------------------------------------------------------------------
// Tensor-core flash attention (tf32 m16n8k8, fp32 softmax).
// Block = 128 threads (4 warps), q-tile 64 rows, key-tile 64.
// Warp w owns q-rows [w*16, w*16+16). Q A-fragments persistent in registers.
// Scores softmaxed in C-fragment registers; P reused as A-fragment of PV with
// the column permutation folded into V's fragment row indexing (k=q -> rows
// 2q, 2q+1). All smem fragment loads conflict-free via stride-68 padding.
// ---------------------------------------------------------------------------
#define ATTN_SMEM_BYTES (3 * 64 * 68 * 4)

__global__ void __launch_bounds__(128)
attn_tc_kernel(const float* __restrict__ Q, const float* __restrict__ K,
               const float* __restrict__ V, const float* __restrict__ alibi,
               float* __restrict__ O)
{
    extern __shared__ uint32_t smem_u[];
    uint32_t (*Qs)[68] = (uint32_t (*)[68])(smem_u);
    uint32_t (*Ks)[68] = (uint32_t (*)[68])(smem_u + 64 * 68);
    uint32_t (*Vs)[68] = (uint32_t (*)[68])(smem_u + 2 * 64 * 68);

    const int bh = blockIdx.y;
    const int b  = bh / H_;
    const int h  = bh % H_;
    const int q0 = blockIdx.x * 64;
    const float slope = alibi[(size_t)h * S_ * S_ + 1];

    const int tid  = threadIdx.x;
    const int lane = tid & 31;
    const int warp = tid >> 5;
    const int gr = lane >> 2;       // 0..7
    const int qq = lane & 3;        // 0..3

    // ---- load Q tile, pre-scaled by 1/sqrt(64)=0.125 (exact), as tf32 ----
    const float* qbase = Q + (size_t)(b * S_ + q0) * D_ + h * HD_;
    for (int i = tid; i < 64 * 16; i += 128) {
        int r = i >> 4, c = (i & 15) * 4;
        float4 v4 = *(const float4*)(qbase + (size_t)r * D_ + c);
        Qs[r][c + 0] = f2tf32(v4.x * 0.125f);
        Qs[r][c + 1] = f2tf32(v4.y * 0.125f);
        Qs[r][c + 2] = f2tf32(v4.z * 0.125f);
        Qs[r][c + 3] = f2tf32(v4.w * 0.125f);
    }
    __syncthreads();

    // ---- persistent Q A-fragments: rows warp*16+gr(+8), cols ks*8+qq(+4) ----
    uint32_t qf[8][4];
    const int qr = warp * 16 + gr;
#pragma unroll
    for (int ks = 0; ks < 8; ++ks) {
        qf[ks][0] = Qs[qr][ks * 8 + qq];
        qf[ks][1] = Qs[qr + 8][ks * 8 + qq];
        qf[ks][2] = Qs[qr][ks * 8 + qq + 4];
        qf[ks][3] = Qs[qr + 8][ks * 8 + qq + 4];
    }

    float m0 = -1e30f, m1 = -1e30f, l0 = 0.f, l1 = 0.f;
    float oacc[8][4];
#pragma unroll
    for (int di = 0; di < 8; ++di)
#pragma unroll
        for (int r = 0; r < 4; ++r) oacc[di][r] = 0.f;

    const int gi0 = q0 + warp * 16 + gr;
    const int gi1 = gi0 + 8;

    const int ktiles = q0 / 64 + 1;     // causal tile skip
    for (int kt = 0; kt < ktiles; ++kt) {
        const int k0 = kt * 64;
        __syncthreads();                // prior iteration done reading Ks/Vs
        const float* kbase = K + (size_t)(b * S_ + k0) * D_ + h * HD_;
        const float* vbase = V + (size_t)(b * S_ + k0) * D_ + h * HD_;
        for (int i = tid; i < 64 * 16; i += 128) {
            int r = i >> 4, c = (i & 15) * 4;
            float4 kv = *(const float4*)(kbase + (size_t)r * D_ + c);
            float4 vv = *(const float4*)(vbase + (size_t)r * D_ + c);
            Ks[r][c + 0] = f2tf32(kv.x); Ks[r][c + 1] = f2tf32(kv.y);
            Ks[r][c + 2] = f2tf32(kv.z); Ks[r][c + 3] = f2tf32(kv.w);
            Vs[r][c + 0] = f2tf32(vv.x); Vs[r][c + 1] = f2tf32(vv.y);
            Vs[r][c + 2] = f2tf32(vv.z); Vs[r][c + 3] = f2tf32(vv.w);
        }
        __syncthreads();

        // ---- scores: S = (Q*0.125) K^T  (8 key-group tiles of 8) ----
        float sc[8][4];
#pragma unroll
        for (int ni = 0; ni < 8; ++ni) {
            sc[ni][0] = 0.f; sc[ni][1] = 0.f; sc[ni][2] = 0.f; sc[ni][3] = 0.f;
#pragma unroll
            for (int ks = 0; ks < 8; ++ks) {
                uint32_t bf[2];
                bf[0] = Ks[ni * 8 + gr][ks * 8 + qq];
                bf[1] = Ks[ni * 8 + gr][ks * 8 + qq + 4];
                mma_tf32(sc[ni], qf[ks], bf);
            }
        }

        // ---- ALiBi + causal + online softmax (in registers) ----
        float rmax0 = -1e30f, rmax1 = -1e30f;
#pragma unroll
        for (int ni = 0; ni < 8; ++ni) {
            const int gj0 = k0 + ni * 8 + qq * 2;
            const int gj1 = gj0 + 1;
            sc[ni][0] = (gj0 <= gi0) ? sc[ni][0] + slope * (float)(gj0 - gi0) : -1e30f;
            sc[ni][1] = (gj1 <= gi0) ? sc[ni][1] + slope * (float)(gj1 - gi0) : -1e30f;
            sc[ni][2] = (gj0 <= gi1) ? sc[ni][2] + slope * (float)(gj0 - gi1) : -1e30f;
            sc[ni][3] = (gj1 <= gi1) ? sc[ni][3] + slope * (float)(gj1 - gi1) : -1e30f;
            rmax0 = fmaxf(rmax0, fmaxf(sc[ni][0], sc[ni][1]));
            rmax1 = fmaxf(rmax1, fmaxf(sc[ni][2], sc[ni][3]));
        }
        rmax0 = fmaxf(rmax0, __shfl_xor_sync(0xffffffffu, rmax0, 1));
        rmax0 = fmaxf(rmax0, __shfl_xor_sync(0xffffffffu, rmax0, 2));
        rmax1 = fmaxf(rmax1, __shfl_xor_sync(0xffffffffu, rmax1, 1));
        rmax1 = fmaxf(rmax1, __shfl_xor_sync(0xffffffffu, rmax1, 2));

        const float mn0 = fmaxf(m0, rmax0);
        const float mn1 = fmaxf(m1, rmax1);
        const float corr0 = __expf(m0 - mn0);
        const float corr1 = __expf(m1 - mn1);

        float rs0 = 0.f, rs1 = 0.f;
        uint32_t pf[8][4];
#pragma unroll
        for (int ni = 0; ni < 8; ++ni) {
            float p0 = __expf(sc[ni][0] - mn0);
            float p1 = __expf(sc[ni][1] - mn0);
            float p2 = __expf(sc[ni][2] - mn1);
            float p3 = __expf(sc[ni][3] - mn1);
            rs0 += p0 + p1;
            rs1 += p2 + p3;
            // C-frag {c0,c1,c2,c3} -> A-frag {a0,a1,a2,a3} = {c0,c2,c1,c3}
            pf[ni][0] = f2tf32(p0);
            pf[ni][1] = f2tf32(p2);
            pf[ni][2] = f2tf32(p1);
            pf[ni][3] = f2tf32(p3);
        }
        rs0 += __shfl_xor_sync(0xffffffffu, rs0, 1);
        rs0 += __shfl_xor_sync(0xffffffffu, rs0, 2);
        rs1 += __shfl_xor_sync(0xffffffffu, rs1, 1);
        rs1 += __shfl_xor_sync(0xffffffffu, rs1, 2);

        l0 = l0 * corr0 + rs0;
        l1 = l1 * corr1 + rs1;
        m0 = mn0; m1 = mn1;

#pragma unroll
        for (int di = 0; di < 8; ++di) {
            oacc[di][0] *= corr0; oacc[di][1] *= corr0;
            oacc[di][2] *= corr1; oacc[di][3] *= corr1;
        }

        // ---- O += P V : V fragment rows permuted (k=q -> rows 2q,2q+1) ----
#pragma unroll
        for (int di = 0; di < 8; ++di) {
#pragma unroll
            for (int ks = 0; ks < 8; ++ks) {
                uint32_t bf[2];
                bf[0] = Vs[ks * 8 + qq * 2][di * 8 + gr];
                bf[1] = Vs[ks * 8 + qq * 2 + 1][di * 8 + gr];
                mma_tf32(oacc[di], pf[ks], bf);
            }
        }
    }

    // ---- write context, (b,s,h,hd) layout ----
    const float inv0 = 1.f / l0;
    const float inv1 = 1.f / l1;
    const size_t row0 = (size_t)(b * S_ + q0 + warp * 16 + gr);
#pragma unroll
    for (int di = 0; di < 8; ++di) {
        const int col = h * HD_ + di * 8 + qq * 2;
        *(float2*)&O[row0 * D_ + col] =
            make_float2(oacc[di][0] * inv0, oacc[di][1] * inv0);
        *(float2*)&O[(row0 + 8) * D_ + col] =
            make_float2(oacc[di][2] * inv1, oacc[di][3] * inv1);
    }
}

// ---------------------------------------------------------------------------
// out = LayerNorm(A_row + B_row) * g + beta ;  row length 768, 256 threads.
// ---------------------------------------------------------------------------
__global__ void __launch_bounds__(256)
add_ln_kernel(const float* __restrict__ A, const float* __restrict__ Bm,
              const float* __restrict__ g, const float* __restrict__ beta,
              float* __restrict__ out)
{
    const int row = blockIdx.x;
    const int tid = threadIdx.x;
    const float* a = A  + (size_t)row * D_;
    const float* b = Bm + (size_t)row * D_;

    float v[3], s = 0.f, ss = 0.f;
#pragma unroll
    for (int i = 0; i < 3; ++i) {
        int c = tid + i * 256;
        v[i] = a[c] + b[c];
        s  += v[i];
        ss += v[i] * v[i];
    }
#pragma unroll
    for (int o = 16; o > 0; o >>= 1) {
        s  += __shfl_xor_sync(0xffffffffu, s,  o);
        ss += __shfl_xor_sync(0xffffffffu, ss, o);
    }
    __shared__ float shs[8], shss[8];
    if ((tid & 31) == 0) { shs[tid >> 5] = s; shss[tid >> 5] = ss; }
    __syncthreads();
    __shared__ float sh_mean, sh_inv;
    if (tid == 0) {
        float ts = 0.f, tss = 0.f;
#pragma unroll
        for (int w = 0; w < 8; ++w) { ts += shs[w]; tss += shss[w]; }
        float mean = ts * (1.f / D_);
        float var  = tss * (1.f / D_) - mean * mean;
        sh_mean = mean;
        sh_inv  = rsqrtf(var + 1e-5f);
    }
    __syncthreads();
    const float mean = sh_mean, inv = sh_inv;
    float* o = out + (size_t)row * D_;
#pragma unroll
    for (int i = 0; i < 3; ++i) {
        int c = tid + i * 256;
        o[c] = (v[i] - mean) * inv * g[c] + beta[c];
    }
}

// ---------------------------------------------------------------------------
static void* sym_addr(const void* symbol) {
    void* p = nullptr;
    cudaGetSymbolAddress(&p, symbol);
    return p;
}

extern "C" void kernel_launch(void* const* d_in, const int* in_sizes, int n_in,
                              void* d_out, int out_size)
{
    const float* x     = (const float*)d_in[0];
    // d_in[1] = mask (unused: causal handled analytically)
    const float* alibi = (const float*)d_in[2];
    const float* wq = (const float*)d_in[3];
    const float* bq = (const float*)d_in[4];
    const float* wk = (const float*)d_in[5];
    const float* bk = (const float*)d_in[6];
    const float* wv = (const float*)d_in[7];
    const float* bv = (const float*)d_in[8];
    const float* wo = (const float*)d_in[9];
    const float* bo = (const float*)d_in[10];
    const float* w1 = (const float*)d_in[11];
    const float* b1 = (const float*)d_in[12];
    const float* w2 = (const float*)d_in[13];
    const float* b2 = (const float*)d_in[14];
    const float* g1 = (const float*)d_in[15];
    const float* be1= (const float*)d_in[16];
    const float* g2 = (const float*)d_in[17];
    const float* be2= (const float*)d_in[18];
    float* out = (float*)d_out;

    float* q   = (float*)sym_addr(gQ);
    float* k   = (float*)sym_addr(gK);
    float* v   = (float*)sym_addr(gV);
    float* ctx = (float*)sym_addr(gCtx);
    float* tmp = (float*)sym_addr(gTmp);
    float* x1  = (float*)sym_addr(gX1);
    float* ff  = (float*)sym_addr(gFF);

    cudaFuncSetAttribute(attn_tc_kernel,
                         cudaFuncAttributeMaxDynamicSharedMemorySize,
                         ATTN_SMEM_BYTES);

    // QKV projections: (4096 x 768) x (768 x 768)^T   [tf32 tensor cores]
    dim3 gproj(D_ / 128, ROWS / 128);
    gemm_tf32<0><<<gproj, 256>>>(x, wq, bq, q, D_, D_);
    gemm_tf32<0><<<gproj, 256>>>(x, wk, bk, k, D_, D_);
    gemm_tf32<0><<<gproj, 256>>>(x, wv, bv, v, D_, D_);

    // attention (tf32 tensor cores, fp32 softmax)
    dim3 gattn(S_ / 64, B_ * H_);
    attn_tc_kernel<<<gattn, 128, ATTN_SMEM_BYTES>>>(q, k, v, alibi, ctx);

    // output projection, residual + LN1
    gemm_tf32<0><<<gproj, 256>>>(ctx, wo, bo, tmp, D_, D_);
    add_ln_kernel<<<ROWS, 256>>>(x, tmp, g1, be1, x1);

    // FFN
    dim3 gff1(FF_ / 128, ROWS / 128);
    gemm_tf32<1><<<gff1, 256>>>(x1, w1, b1, ff, FF_, D_);
    gemm_tf32<0><<<gproj, 256>>>(ff, w2, b2, tmp, D_, FF_);

    // residual + LN2 -> output
    add_ln_kernel<<<ROWS, 256>>>(x1, tmp, g2, be2, out);
}

// round 12
// speedup vs baseline: 3.0399x; 1.0644x over previous
#include <cuda_runtime.h>
#include <cstdint>

#define B_  2
#define S_  2048
#define D_  768
#define H_  12
#define HD_ 64
#define FF_ 3072
#define ROWS (B_ * S_)   // 4096

// ---------------- scratch (device globals; no allocation allowed) ----------
__device__ float gQ  [ROWS * D_];
__device__ float gK  [ROWS * D_];
__device__ float gV  [ROWS * D_];
__device__ float gCtx[ROWS * D_];
__device__ float gTmp[ROWS * D_];
__device__ float gX1 [ROWS * D_];
__device__ float gFF [ROWS * FF_];

// ---------------------------------------------------------------------------
__device__ __forceinline__ uint32_t f2tf32(float x) {
    uint32_t u;
    asm("cvt.rna.tf32.f32 %0, %1;" : "=r"(u) : "f"(x));
    return u;
}

__device__ __forceinline__ void mma_tf32(float* c, const uint32_t* a, const uint32_t* b) {
    asm volatile(
        "mma.sync.aligned.m16n8k8.row.col.f32.tf32.tf32.f32 "
        "{%0,%1,%2,%3}, {%4,%5,%6,%7}, {%8,%9}, {%0,%1,%2,%3};"
        : "+f"(c[0]), "+f"(c[1]), "+f"(c[2]), "+f"(c[3])
        : "r"(a[0]), "r"(a[1]), "r"(a[2]), "r"(a[3]), "r"(b[0]), "r"(b[1]));
}

// swizzled index into a [128][16] subtile (proven conflict-free in R5)
__device__ __forceinline__ int swz(int r, int c) {
    return r * 16 + (c ^ (((r >> 1) & 3) << 2));
}

// ---------------------------------------------------------------------------
// tf32 GEMM (NT), BK=32, 2-stage smem double buffer, one barrier per k-iter.
// Block 128x128, 256 threads = 8 warps (2M x 4N), warp tile 64x32.
// smem: [stage][matrix][sub 16-col][128x16 swizzled] = 64 KB dynamic.
// C[m,n] = sum_k A[m,k]*B[n,k] + bias[n], optional ReLU.
// ---------------------------------------------------------------------------
#define GEMM_SMEM_BYTES (2 * 2 * 2 * 2048 * 4)   // 65536

template <int RELU>
__device__ __forceinline__ void
gemm_db_body(const float* __restrict__ A, const float* __restrict__ Bm,
             const float* __restrict__ bias, float* __restrict__ C,
             int N, int K, int bm, int bn, uint32_t* sm)
{
    // layout: stage st, matrix (A=0,B=1), subtile sub -> sm + ((st*2+mat)*2 + sub)*2048
    const int tid  = threadIdx.x;
    const int lane = tid & 31;
    const int warp = tid >> 5;

    const int m_base = (warp >> 2) * 64;
    const int n_base = (warp & 3) * 32;
    const int gr = lane >> 2;
    const int qq = lane & 3;

    const int lr = tid >> 2;            // 0..63
    const int lc = (tid & 3) * 4;       // 0,4,8,12

    float acc[4][4][4];
#pragma unroll
    for (int mi = 0; mi < 4; ++mi)
#pragma unroll
        for (int ni = 0; ni < 4; ++ni)
#pragma unroll
            for (int r = 0; r < 4; ++r) acc[mi][ni][r] = 0.f;

    float4 areg[2][2], breg[2][2];      // [half][sub]

    auto ldtile = [&](int k0) {
#pragma unroll
        for (int h = 0; h < 2; ++h)
#pragma unroll
            for (int sub = 0; sub < 2; ++sub) {
                areg[h][sub] = *(const float4*)(A  + (size_t)(bm + lr + 64 * h) * K + k0 + sub * 16 + lc);
                breg[h][sub] = *(const float4*)(Bm + (size_t)(bn + lr + 64 * h) * K + k0 + sub * 16 + lc);
            }
    };
    auto sttile = [&](int st) {
#pragma unroll
        for (int h = 0; h < 2; ++h)
#pragma unroll
            for (int sub = 0; sub < 2; ++sub) {
                uint32_t* pa = sm + ((st * 2 + 0) * 2 + sub) * 2048 + swz(lr + 64 * h, lc);
                uint32_t* pb = sm + ((st * 2 + 1) * 2 + sub) * 2048 + swz(lr + 64 * h, lc);
                pa[0] = f2tf32(areg[h][sub].x); pa[1] = f2tf32(areg[h][sub].y);
                pa[2] = f2tf32(areg[h][sub].z); pa[3] = f2tf32(areg[h][sub].w);
                pb[0] = f2tf32(breg[h][sub].x); pb[1] = f2tf32(breg[h][sub].y);
                pb[2] = f2tf32(breg[h][sub].z); pb[3] = f2tf32(breg[h][sub].w);
            }
    };

    ldtile(0);
    sttile(0);
    __syncthreads();

    int st = 0;
    for (int k0 = 0; k0 < K; k0 += 32) {
        const bool more = (k0 + 32 < K);
        if (more) ldtile(k0 + 32);      // prefetch under MMA

#pragma unroll
        for (int ks = 0; ks < 4; ++ks) {
            const uint32_t* as = sm + ((st * 2 + 0) * 2 + (ks >> 1)) * 2048;
            const uint32_t* bs = sm + ((st * 2 + 1) * 2 + (ks >> 1)) * 2048;
            const int cb = (ks & 1) * 8;
            uint32_t a[4][4], b[4][2];
#pragma unroll
            for (int mi = 0; mi < 4; ++mi) {
                const int r0 = m_base + mi * 16 + gr;
                a[mi][0] = as[swz(r0,     cb + qq)];
                a[mi][1] = as[swz(r0 + 8, cb + qq)];
                a[mi][2] = as[swz(r0,     cb + qq + 4)];
                a[mi][3] = as[swz(r0 + 8, cb + qq + 4)];
            }
#pragma unroll
            for (int ni = 0; ni < 4; ++ni) {
                const int nn = n_base + ni * 8 + gr;
                b[ni][0] = bs[swz(nn, cb + qq)];
                b[ni][1] = bs[swz(nn, cb + qq + 4)];
            }
#pragma unroll
            for (int mi = 0; mi < 4; ++mi)
#pragma unroll
                for (int ni = 0; ni < 4; ++ni)
                    mma_tf32(acc[mi][ni], a[mi], b[ni]);
        }

        if (more) {
            sttile(st ^ 1);             // other buffer: safe while st is read
            __syncthreads();
            st ^= 1;
        }
    }

    const int gc = qq * 2;
#pragma unroll
    for (int ni = 0; ni < 4; ++ni) {
        const int n0 = bn + n_base + ni * 8 + gc;
        const float bv0 = bias[n0], bv1 = bias[n0 + 1];
#pragma unroll
        for (int mi = 0; mi < 4; ++mi) {
            const int row = bm + m_base + mi * 16 + gr;
            float2 v0 = make_float2(acc[mi][ni][0] + bv0, acc[mi][ni][1] + bv1);
            float2 v1 = make_float2(acc[mi][ni][2] + bv0, acc[mi][ni][3] + bv1);
            if (RELU) {
                v0.x = fmaxf(v0.x, 0.f); v0.y = fmaxf(v0.y, 0.f);
                v1.x = fmaxf(v1.x, 0.f); v1.y = fmaxf(v1.y, 0.f);
            }
            *(float2*)&C[(size_t)row * N + n0]       = v0;
            *(float2*)&C[(size_t)(row + 8) * N + n0] = v1;
        }
    }
}

template <int RELU>
__global__ void __launch_bounds__(256)
gemm_tf32_db(const float* __restrict__ A, const float* __restrict__ Bm,
             const float* __restrict__ bias, float* __restrict__ C,
             int N, int K)
{
    extern __shared__ uint32_t sm[];
    gemm_db_body<RELU>(A, Bm, bias, C, N, K, blockIdx.y * 128, blockIdx.x * 128, sm);
}

// fused QKV: one launch, blockIdx.z selects weight/bias/output
__global__ void __launch_bounds__(256)
gemm_qkv(const float* __restrict__ x,
         const float* __restrict__ wq, const float* __restrict__ bq,
         const float* __restrict__ wk, const float* __restrict__ bk,
         const float* __restrict__ wv, const float* __restrict__ bv,
         float* __restrict__ q, float* __restrict__ k, float* __restrict__ v)
{
    extern __shared__ uint32_t sm[];
    const float* W; const float* bb; float* out;
    if (blockIdx.z == 0)      { W = wq; bb = bq; out = q; }
    else if (blockIdx.z == 1) { W = wk; bb = bk; out = k; }
    else                      { W = wv; bb = bv; out = v; }
    gemm_db_body<0>(x, W, bb, out, D_, D_, blockIdx.y * 128, blockIdx.x * 128, sm);
}

// ---------------------------------------------------------------------------
// Tensor-core flash attention (tf32 m16n8k8, fp32 softmax) — unchanged (R7).
// ---------------------------------------------------------------------------
#define ATTN_SMEM_BYTES (3 * 64 * 68 * 4)

__global__ void __launch_bounds__(128)
attn_tc_kernel(const float* __restrict__ Q, const float* __restrict__ K,
               const float* __restrict__ V, const float* __restrict__ alibi,
               float* __restrict__ O)
{
    extern __shared__ uint32_t smem_u[];
    uint32_t (*Qs)[68] = (uint32_t (*)[68])(smem_u);
    uint32_t (*Ks)[68] = (uint32_t (*)[68])(smem_u + 64 * 68);
    uint32_t (*Vs)[68] = (uint32_t (*)[68])(smem_u + 2 * 64 * 68);

    const int bh = blockIdx.y;
    const int b  = bh / H_;
    const int h  = bh % H_;
    const int q0 = blockIdx.x * 64;
    const float slope = alibi[(size_t)h * S_ * S_ + 1];

    const int tid  = threadIdx.x;
    const int lane = tid & 31;
    const int warp = tid >> 5;
    const int gr = lane >> 2;
    const int qq = lane & 3;

    const float* qbase = Q + (size_t)(b * S_ + q0) * D_ + h * HD_;
    for (int i = tid; i < 64 * 16; i += 128) {
        int r = i >> 4, c = (i & 15) * 4;
        float4 v4 = *(const float4*)(qbase + (size_t)r * D_ + c);
        Qs[r][c + 0] = f2tf32(v4.x * 0.125f);
        Qs[r][c + 1] = f2tf32(v4.y * 0.125f);
        Qs[r][c + 2] = f2tf32(v4.z * 0.125f);
        Qs[r][c + 3] = f2tf32(v4.w * 0.125f);
    }
    __syncthreads();

    uint32_t qf[8][4];
    const int qr = warp * 16 + gr;
#pragma unroll
    for (int ks = 0; ks < 8; ++ks) {
        qf[ks][0] = Qs[qr][ks * 8 + qq];
        qf[ks][1] = Qs[qr + 8][ks * 8 + qq];
        qf[ks][2] = Qs[qr][ks * 8 + qq + 4];
        qf[ks][3] = Qs[qr + 8][ks * 8 + qq + 4];
    }

    float m0 = -1e30f, m1 = -1e30f, l0 = 0.f, l1 = 0.f;
    float oacc[8][4];
#pragma unroll
    for (int di = 0; di < 8; ++di)
#pragma unroll
        for (int r = 0; r < 4; ++r) oacc[di][r] = 0.f;

    const int gi0 = q0 + warp * 16 + gr;
    const int gi1 = gi0 + 8;

    const int ktiles = q0 / 64 + 1;
    for (int kt = 0; kt < ktiles; ++kt) {
        const int k0 = kt * 64;
        __syncthreads();
        const float* kbase = K + (size_t)(b * S_ + k0) * D_ + h * HD_;
        const float* vbase = V + (size_t)(b * S_ + k0) * D_ + h * HD_;
        for (int i = tid; i < 64 * 16; i += 128) {
            int r = i >> 4, c = (i & 15) * 4;
            float4 kv = *(const float4*)(kbase + (size_t)r * D_ + c);
            float4 vv = *(const float4*)(vbase + (size_t)r * D_ + c);
            Ks[r][c + 0] = f2tf32(kv.x); Ks[r][c + 1] = f2tf32(kv.y);
            Ks[r][c + 2] = f2tf32(kv.z); Ks[r][c + 3] = f2tf32(kv.w);
            Vs[r][c + 0] = f2tf32(vv.x); Vs[r][c + 1] = f2tf32(vv.y);
            Vs[r][c + 2] = f2tf32(vv.z); Vs[r][c + 3] = f2tf32(vv.w);
        }
        __syncthreads();

        float sc[8][4];
#pragma unroll
        for (int ni = 0; ni < 8; ++ni) {
            sc[ni][0] = 0.f; sc[ni][1] = 0.f; sc[ni][2] = 0.f; sc[ni][3] = 0.f;
#pragma unroll
            for (int ks = 0; ks < 8; ++ks) {
                uint32_t bf[2];
                bf[0] = Ks[ni * 8 + gr][ks * 8 + qq];
                bf[1] = Ks[ni * 8 + gr][ks * 8 + qq + 4];
                mma_tf32(sc[ni], qf[ks], bf);
            }
        }

        float rmax0 = -1e30f, rmax1 = -1e30f;
#pragma unroll
        for (int ni = 0; ni < 8; ++ni) {
            const int gj0 = k0 + ni * 8 + qq * 2;
            const int gj1 = gj0 + 1;
            sc[ni][0] = (gj0 <= gi0) ? sc[ni][0] + slope * (float)(gj0 - gi0) : -1e30f;
            sc[ni][1] = (gj1 <= gi0) ? sc[ni][1] + slope * (float)(gj1 - gi0) : -1e30f;
            sc[ni][2] = (gj0 <= gi1) ? sc[ni][2] + slope * (float)(gj0 - gi1) : -1e30f;
            sc[ni][3] = (gj1 <= gi1) ? sc[ni][3] + slope * (float)(gj1 - gi1) : -1e30f;
            rmax0 = fmaxf(rmax0, fmaxf(sc[ni][0], sc[ni][1]));
            rmax1 = fmaxf(rmax1, fmaxf(sc[ni][2], sc[ni][3]));
        }
        rmax0 = fmaxf(rmax0, __shfl_xor_sync(0xffffffffu, rmax0, 1));
        rmax0 = fmaxf(rmax0, __shfl_xor_sync(0xffffffffu, rmax0, 2));
        rmax1 = fmaxf(rmax1, __shfl_xor_sync(0xffffffffu, rmax1, 1));
        rmax1 = fmaxf(rmax1, __shfl_xor_sync(0xffffffffu, rmax1, 2));

        const float mn0 = fmaxf(m0, rmax0);
        const float mn1 = fmaxf(m1, rmax1);
        const float corr0 = __expf(m0 - mn0);
        const float corr1 = __expf(m1 - mn1);

        float rs0 = 0.f, rs1 = 0.f;
        uint32_t pf[8][4];
#pragma unroll
        for (int ni = 0; ni < 8; ++ni) {
            float p0 = __expf(sc[ni][0] - mn0);
            float p1 = __expf(sc[ni][1] - mn0);
            float p2 = __expf(sc[ni][2] - mn1);
            float p3 = __expf(sc[ni][3] - mn1);
            rs0 += p0 + p1;
            rs1 += p2 + p3;
            pf[ni][0] = f2tf32(p0);
            pf[ni][1] = f2tf32(p2);
            pf[ni][2] = f2tf32(p1);
            pf[ni][3] = f2tf32(p3);
        }
        rs0 += __shfl_xor_sync(0xffffffffu, rs0, 1);
        rs0 += __shfl_xor_sync(0xffffffffu, rs0, 2);
        rs1 += __shfl_xor_sync(0xffffffffu, rs1, 1);
        rs1 += __shfl_xor_sync(0xffffffffu, rs1, 2);

        l0 = l0 * corr0 + rs0;
        l1 = l1 * corr1 + rs1;
        m0 = mn0; m1 = mn1;

#pragma unroll
        for (int di = 0; di < 8; ++di) {
            oacc[di][0] *= corr0; oacc[di][1] *= corr0;
            oacc[di][2] *= corr1; oacc[di][3] *= corr1;
        }

#pragma unroll
        for (int di = 0; di < 8; ++di) {
#pragma unroll
            for (int ks = 0; ks < 8; ++ks) {
                uint32_t bf[2];
                bf[0] = Vs[ks * 8 + qq * 2][di * 8 + gr];
                bf[1] = Vs[ks * 8 + qq * 2 + 1][di * 8 + gr];
                mma_tf32(oacc[di], pf[ks], bf);
            }
        }
    }

    const float inv0 = 1.f / l0;
    const float inv1 = 1.f / l1;
    const size_t row0 = (size_t)(b * S_ + q0 + warp * 16 + gr);
#pragma unroll
    for (int di = 0; di < 8; ++di) {
        const int col = h * HD_ + di * 8 + qq * 2;
        *(float2*)&O[row0 * D_ + col] =
            make_float2(oacc[di][0] * inv0, oacc[di][1] * inv0);
        *(float2*)&O[(row0 + 8) * D_ + col] =
            make_float2(oacc[di][2] * inv1, oacc[di][3] * inv1);
    }
}

// ---------------------------------------------------------------------------
// out = LayerNorm(A_row + B_row) * g + beta ;  row length 768, 256 threads.
// ---------------------------------------------------------------------------
__global__ void __launch_bounds__(256)
add_ln_kernel(const float* __restrict__ A, const float* __restrict__ Bm,
              const float* __restrict__ g, const float* __restrict__ beta,
              float* __restrict__ out)
{
    const int row = blockIdx.x;
    const int tid = threadIdx.x;
    const float* a = A  + (size_t)row * D_;
    const float* b = Bm + (size_t)row * D_;

    float v[3], s = 0.f, ss = 0.f;
#pragma unroll
    for (int i = 0; i < 3; ++i) {
        int c = tid + i * 256;
        v[i] = a[c] + b[c];
        s  += v[i];
        ss += v[i] * v[i];
    }
#pragma unroll
    for (int o = 16; o > 0; o >>= 1) {
        s  += __shfl_xor_sync(0xffffffffu, s,  o);
        ss += __shfl_xor_sync(0xffffffffu, ss, o);
    }
    __shared__ float shs[8], shss[8];
    if ((tid & 31) == 0) { shs[tid >> 5] = s; shss[tid >> 5] = ss; }
    __syncthreads();
    __shared__ float sh_mean, sh_inv;
    if (tid == 0) {
        float ts = 0.f, tss = 0.f;
#pragma unroll
        for (int w = 0; w < 8; ++w) { ts += shs[w]; tss += shss[w]; }
        float mean = ts * (1.f / D_);
        float var  = tss * (1.f / D_) - mean * mean;
        sh_mean = mean;
        sh_inv  = rsqrtf(var + 1e-5f);
    }
    __syncthreads();
    const float mean = sh_mean, inv = sh_inv;
    float* o = out + (size_t)row * D_;
#pragma unroll
    for (int i = 0; i < 3; ++i) {
        int c = tid + i * 256;
        o[c] = (v[i] - mean) * inv * g[c] + beta[c];
    }
}

// ---------------------------------------------------------------------------
static void* sym_addr(const void* symbol) {
    void* p = nullptr;
    cudaGetSymbolAddress(&p, symbol);
    return p;
}

extern "C" void kernel_launch(void* const* d_in, const int* in_sizes, int n_in,
                              void* d_out, int out_size)
{
    const float* x     = (const float*)d_in[0];
    // d_in[1] = mask (unused: causal handled analytically)
    const float* alibi = (const float*)d_in[2];
    const float* wq = (const float*)d_in[3];
    const float* bq = (const float*)d_in[4];
    const float* wk = (const float*)d_in[5];
    const float* bk = (const float*)d_in[6];
    const float* wv = (const float*)d_in[7];
    const float* bv = (const float*)d_in[8];
    const float* wo = (const float*)d_in[9];
    const float* bo = (const float*)d_in[10];
    const float* w1 = (const float*)d_in[11];
    const float* b1 = (const float*)d_in[12];
    const float* w2 = (const float*)d_in[13];
    const float* b2 = (const float*)d_in[14];
    const float* g1 = (const float*)d_in[15];
    const float* be1= (const float*)d_in[16];
    const float* g2 = (const float*)d_in[17];
    const float* be2= (const float*)d_in[18];
    float* out = (float*)d_out;

    float* q   = (float*)sym_addr(gQ);
    float* k   = (float*)sym_addr(gK);
    float* v   = (float*)sym_addr(gV);
    float* ctx = (float*)sym_addr(gCtx);
    float* tmp = (float*)sym_addr(gTmp);
    float* x1  = (float*)sym_addr(gX1);
    float* ff  = (float*)sym_addr(gFF);

    cudaFuncSetAttribute(attn_tc_kernel,
                         cudaFuncAttributeMaxDynamicSharedMemorySize,
                         ATTN_SMEM_BYTES);
    cudaFuncSetAttribute(gemm_qkv,
                         cudaFuncAttributeMaxDynamicSharedMemorySize,
                         GEMM_SMEM_BYTES);
    cudaFuncSetAttribute(gemm_tf32_db<0>,
                         cudaFuncAttributeMaxDynamicSharedMemorySize,
                         GEMM_SMEM_BYTES);
    cudaFuncSetAttribute(gemm_tf32_db<1>,
                         cudaFuncAttributeMaxDynamicSharedMemorySize,
                         GEMM_SMEM_BYTES);

    // QKV projections fused into one launch (grid.z = 3)
    dim3 gqkv(D_ / 128, ROWS / 128, 3);
    gemm_qkv<<<gqkv, 256, GEMM_SMEM_BYTES>>>(x, wq, bq, wk, bk, wv, bv, q, k, v);

    // attention (tf32 tensor cores, fp32 softmax)
    dim3 gattn(S_ / 64, B_ * H_);
    attn_tc_kernel<<<gattn, 128, ATTN_SMEM_BYTES>>>(q, k, v, alibi, ctx);

    // output projection, residual + LN1
    dim3 gproj(D_ / 128, ROWS / 128);
    gemm_tf32_db<0><<<gproj, 256, GEMM_SMEM_BYTES>>>(ctx, wo, bo, tmp, D_, D_);
    add_ln_kernel<<<ROWS, 256>>>(x, tmp, g1, be1, x1);

    // FFN
    dim3 gff1(FF_ / 128, ROWS / 128);
    gemm_tf32_db<1><<<gff1, 256, GEMM_SMEM_BYTES>>>(x1, w1, b1, ff, FF_, D_);
    gemm_tf32_db<0><<<gproj, 256, GEMM_SMEM_BYTES>>>(ff, w2, b2, tmp, D_, FF_);

    // residual + LN2 -> output
    add_ln_kernel<<<ROWS, 256>>>(x1, tmp, g2, be2, out);
}

// round 14
// speedup vs baseline: 5.0428x; 1.6589x over previous
#include <cuda_runtime.h>
#include <cstdint>

#define B_  2
#define S_  2048
#define D_  768
#define H_  12
#define HD_ 64
#define FF_ 3072
#define ROWS (B_ * S_)   // 4096

// ---------------- scratch (device globals; no allocation allowed) ----------
__device__ float gQ  [ROWS * D_];
__device__ float gK  [ROWS * D_];
__device__ float gV  [ROWS * D_];
__device__ float gCtx[ROWS * D_];
__device__ float gTmp[ROWS * D_];
__device__ float gX1 [ROWS * D_];
__device__ float gFF [ROWS * FF_];

// ---------------------------------------------------------------------------
// helpers
// ---------------------------------------------------------------------------
__device__ __forceinline__ uint32_t f2tf32(float x) {
    uint32_t u;
    asm("cvt.rna.tf32.f32 %0, %1;" : "=r"(u) : "f"(x));
    return u;
}

__device__ __forceinline__ void mma_tf32(float* c, const uint32_t* a, const uint32_t* b) {
    asm volatile(
        "mma.sync.aligned.m16n8k8.row.col.f32.tf32.tf32.f32 "
        "{%0,%1,%2,%3}, {%4,%5,%6,%7}, {%8,%9}, {%0,%1,%2,%3};"
        : "+f"(c[0]), "+f"(c[1]), "+f"(c[2]), "+f"(c[3])
        : "r"(a[0]), "r"(a[1]), "r"(a[2]), "r"(a[3]), "r"(b[0]), "r"(b[1]));
}

__device__ __forceinline__ uint32_t smem_u32(const void* p) {
    uint32_t a;
    asm("{ .reg .u64 t; cvta.to.shared.u64 t, %1; cvt.u32.u64 %0, t; }"
        : "=r"(a) : "l"(p));
    return a;
}

__device__ __forceinline__ void cp_async16(uint32_t dst, const void* src) {
    asm volatile("cp.async.cg.shared.global [%0], [%1], 16;"
                 :: "r"(dst), "l"(src) : "memory");
}
__device__ __forceinline__ void cp_commit() {
    asm volatile("cp.async.commit_group;" ::: "memory");
}
template <int N>
__device__ __forceinline__ void cp_wait() {
    asm volatile("cp.async.wait_group %0;" :: "n"(N) : "memory");
}

// ---------------------------------------------------------------------------
// tf32 mma.sync GEMM (NT): C[m,n] = sum_k A[m,k]*B[n,k] + bias[n]
// Block 128x128, 128 threads = 4 warps (2M x 2N), warp tile 64x64.
// BK=32, 2-stage cp.async double buffer. Raw fp32 bits fed to tf32 mma
// (HW truncation; no cvt cost). Smem swizzle: 16B chunk index XOR (row&7)
// -> cp.async-compatible AND conflict-free scalar fragment LDS
// (bank = 4*(chunk^gr)+qq, all 32 lanes distinct).
// Per-stage tile: A[128][32]f + B[128][32]f = 32KB; 2 stages = 64KB.
// ---------------------------------------------------------------------------
#define GEMM_SMEM_BYTES 65536

template <int RELU>
__device__ __forceinline__ void
gemm_v3_body(const float* __restrict__ A, const float* __restrict__ Bm,
             const float* __restrict__ bias, float* __restrict__ C,
             int N, int K, int bm, int bn, char* smem)
{
    const uint32_t sbase = smem_u32(smem);
    const int tid  = threadIdx.x;
    const int lane = tid & 31;
    const int warp = tid >> 5;
    const int wm = warp >> 1;           // 0,1 -> M half
    const int wn = warp & 1;            // 0,1 -> N half
    const int gr = lane >> 2;           // 0..7
    const int qq = lane & 3;            // 0..3
    const int nk = K >> 5;

    // loader mapping: thread covers rows (tid>>3)+16j, 16B chunk tid&7
    const int rbase = tid >> 3;         // 0..15
    const int c8    = tid & 7;          // 0..7
    const uint32_t swc = (uint32_t)(c8 ^ (rbase & 7)) << 4;  // row&7==rbase&7

    auto issue_loads = [&](int st, int k0) {
        const uint32_t dA = sbase + st * 32768;
        const uint32_t dB = dA + 16384;
#pragma unroll
        for (int j = 0; j < 8; ++j) {
            const int row = rbase + j * 16;
            const uint32_t off = (uint32_t)row * 128 + swc;
            cp_async16(dA + off, A  + (size_t)(bm + row) * K + k0 + c8 * 4);
            cp_async16(dB + off, Bm + (size_t)(bn + row) * K + k0 + c8 * 4);
        }
        cp_commit();
    };

    float acc[4][8][4];
#pragma unroll
    for (int mi = 0; mi < 4; ++mi)
#pragma unroll
        for (int ni = 0; ni < 8; ++ni)
#pragma unroll
            for (int r = 0; r < 4; ++r) acc[mi][ni][r] = 0.f;

    issue_loads(0, 0);

    for (int c = 0; c < nk; ++c) {
        const int st = c & 1;
        if (c + 1 < nk) {
            issue_loads(st ^ 1, (c + 1) * 32);
            cp_wait<1>();
        } else {
            cp_wait<0>();
        }
        __syncthreads();

        const uint32_t* Au = (const uint32_t*)(smem + st * 32768);
        const uint32_t* Bu = Au + 4096;

#pragma unroll
        for (int ks = 0; ks < 4; ++ks) {
            // swizzled columns for kk=ks*8+qq and kk+4 (row&7 == gr here)
            const int col0 = (((ks * 2)     ^ gr) << 2) + qq;
            const int col1 = (((ks * 2 + 1) ^ gr) << 2) + qq;

            uint32_t a[4][4], b[8][2];
#pragma unroll
            for (int mi = 0; mi < 4; ++mi) {
                const int r0 = wm * 64 + mi * 16 + gr;
                a[mi][0] = Au[r0 * 32 + col0];
                a[mi][1] = Au[(r0 + 8) * 32 + col0];
                a[mi][2] = Au[r0 * 32 + col1];
                a[mi][3] = Au[(r0 + 8) * 32 + col1];
            }
#pragma unroll
            for (int ni = 0; ni < 8; ++ni) {
                const int n = wn * 64 + ni * 8 + gr;
                b[ni][0] = Bu[n * 32 + col0];
                b[ni][1] = Bu[n * 32 + col1];
            }
#pragma unroll
            for (int mi = 0; mi < 4; ++mi)
#pragma unroll
                for (int ni = 0; ni < 8; ++ni)
                    mma_tf32(acc[mi][ni], a[mi], b[ni]);
        }
        __syncthreads();
    }

    // epilogue: c0:(gr,gc) c1:(gr,gc+1) c2:(gr+8,gc) c3:(gr+8,gc+1)
#pragma unroll
    for (int ni = 0; ni < 8; ++ni) {
        const int n0 = bn + wn * 64 + ni * 8 + qq * 2;
        const float2 bv = *(const float2*)&bias[n0];
#pragma unroll
        for (int mi = 0; mi < 4; ++mi) {
            const int row = bm + wm * 64 + mi * 16 + gr;
            float2 v0 = make_float2(acc[mi][ni][0] + bv.x, acc[mi][ni][1] + bv.y);
            float2 v1 = make_float2(acc[mi][ni][2] + bv.x, acc[mi][ni][3] + bv.y);
            if (RELU) {
                v0.x = fmaxf(v0.x, 0.f); v0.y = fmaxf(v0.y, 0.f);
                v1.x = fmaxf(v1.x, 0.f); v1.y = fmaxf(v1.y, 0.f);
            }
            *(float2*)&C[(size_t)row * N + n0]       = v0;
            *(float2*)&C[(size_t)(row + 8) * N + n0] = v1;
        }
    }
}

template <int RELU>
__global__ void __launch_bounds__(128, 2)
gemm_v3(const float* __restrict__ A, const float* __restrict__ Bm,
        const float* __restrict__ bias, float* __restrict__ C, int N, int K)
{
    extern __shared__ char smem[];
    gemm_v3_body<RELU>(A, Bm, bias, C, N, K,
                       blockIdx.y * 128, blockIdx.x * 128, smem);
}

// fused QKV: one launch, blockIdx.z selects weight/bias/output
__global__ void __launch_bounds__(128, 2)
gemm_v3_qkv(const float* __restrict__ x,
            const float* __restrict__ wq, const float* __restrict__ bq,
            const float* __restrict__ wk, const float* __restrict__ bk,
            const float* __restrict__ wv, const float* __restrict__ bv,
            float* __restrict__ q, float* __restrict__ k, float* __restrict__ v)
{
    extern __shared__ char smem[];
    const float* W; const float* bb; float* out;
    if (blockIdx.z == 0)      { W = wq; bb = bq; out = q; }
    else if (blockIdx.z == 1) { W = wk; bb = bk; out = k; }
    else                      { W = wv; bb = bv; out = v; }
    gemm_v3_body<0>(x, W, bb, out, D_, D_, blockIdx.y * 128, blockIdx.x * 128, smem);
}

// ---------------------------------------------------------------------------
// Tensor-core flash attention (tf32 m16n8k8, fp32 softmax) — unchanged (R7).
// ---------------------------------------------------------------------------
#define ATTN_SMEM_BYTES (3 * 64 * 68 * 4)

__global__ void __launch_bounds__(128)
attn_tc_kernel(const float* __restrict__ Q, const float* __restrict__ K,
               const float* __restrict__ V, const float* __restrict__ alibi,
               float* __restrict__ O)
{
    extern __shared__ uint32_t smem_u[];
    uint32_t (*Qs)[68] = (uint32_t (*)[68])(smem_u);
    uint32_t (*Ks)[68] = (uint32_t (*)[68])(smem_u + 64 * 68);
    uint32_t (*Vs)[68] = (uint32_t (*)[68])(smem_u + 2 * 64 * 68);

    const int bh = blockIdx.y;
    const int b  = bh / H_;
    const int h  = bh % H_;
    const int q0 = blockIdx.x * 64;
    const float slope = alibi[(size_t)h * S_ * S_ + 1];

    const int tid  = threadIdx.x;
    const int lane = tid & 31;
    const int warp = tid >> 5;
    const int gr = lane >> 2;
    const int qq = lane & 3;

    const float* qbase = Q + (size_t)(b * S_ + q0) * D_ + h * HD_;
    for (int i = tid; i < 64 * 16; i += 128) {
        int r = i >> 4, c = (i & 15) * 4;
        float4 v4 = *(const float4*)(qbase + (size_t)r * D_ + c);
        Qs[r][c + 0] = f2tf32(v4.x * 0.125f);
        Qs[r][c + 1] = f2tf32(v4.y * 0.125f);
        Qs[r][c + 2] = f2tf32(v4.z * 0.125f);
        Qs[r][c + 3] = f2tf32(v4.w * 0.125f);
    }
    __syncthreads();

    uint32_t qf[8][4];
    const int qr = warp * 16 + gr;
#pragma unroll
    for (int ks = 0; ks < 8; ++ks) {
        qf[ks][0] = Qs[qr][ks * 8 + qq];
        qf[ks][1] = Qs[qr + 8][ks * 8 + qq];
        qf[ks][2] = Qs[qr][ks * 8 + qq + 4];
        qf[ks][3] = Qs[qr + 8][ks * 8 + qq + 4];
    }

    float m0 = -1e30f, m1 = -1e30f, l0 = 0.f, l1 = 0.f;
    float oacc[8][4];
#pragma unroll
    for (int di = 0; di < 8; ++di)
#pragma unroll
        for (int r = 0; r < 4; ++r) oacc[di][r] = 0.f;

    const int gi0 = q0 + warp * 16 + gr;
    const int gi1 = gi0 + 8;

    const int ktiles = q0 / 64 + 1;
    for (int kt = 0; kt < ktiles; ++kt) {
        const int k0 = kt * 64;
        __syncthreads();
        const float* kbase = K + (size_t)(b * S_ + k0) * D_ + h * HD_;
        const float* vbase = V + (size_t)(b * S_ + k0) * D_ + h * HD_;
        for (int i = tid; i < 64 * 16; i += 128) {
            int r = i >> 4, c = (i & 15) * 4;
            float4 kv = *(const float4*)(kbase + (size_t)r * D_ + c);
            float4 vv = *(const float4*)(vbase + (size_t)r * D_ + c);
            Ks[r][c + 0] = f2tf32(kv.x); Ks[r][c + 1] = f2tf32(kv.y);
            Ks[r][c + 2] = f2tf32(kv.z); Ks[r][c + 3] = f2tf32(kv.w);
            Vs[r][c + 0] = f2tf32(vv.x); Vs[r][c + 1] = f2tf32(vv.y);
            Vs[r][c + 2] = f2tf32(vv.z); Vs[r][c + 3] = f2tf32(vv.w);
        }
        __syncthreads();

        float sc[8][4];
#pragma unroll
        for (int ni = 0; ni < 8; ++ni) {
            sc[ni][0] = 0.f; sc[ni][1] = 0.f; sc[ni][2] = 0.f; sc[ni][3] = 0.f;
#pragma unroll
            for (int ks = 0; ks < 8; ++ks) {
                uint32_t bf[2];
                bf[0] = Ks[ni * 8 + gr][ks * 8 + qq];
                bf[1] = Ks[ni * 8 + gr][ks * 8 + qq + 4];
                mma_tf32(sc[ni], qf[ks], bf);
            }
        }

        float rmax0 = -1e30f, rmax1 = -1e30f;
#pragma unroll
        for (int ni = 0; ni < 8; ++ni) {
            const int gj0 = k0 + ni * 8 + qq * 2;
            const int gj1 = gj0 + 1;
            sc[ni][0] = (gj0 <= gi0) ? sc[ni][0] + slope * (float)(gj0 - gi0) : -1e30f;
            sc[ni][1] = (gj1 <= gi0) ? sc[ni][1] + slope * (float)(gj1 - gi0) : -1e30f;
            sc[ni][2] = (gj0 <= gi1) ? sc[ni][2] + slope * (float)(gj0 - gi1) : -1e30f;
            sc[ni][3] = (gj1 <= gi1) ? sc[ni][3] + slope * (float)(gj1 - gi1) : -1e30f;
            rmax0 = fmaxf(rmax0, fmaxf(sc[ni][0], sc[ni][1]));
            rmax1 = fmaxf(rmax1, fmaxf(sc[ni][2], sc[ni][3]));
        }
        rmax0 = fmaxf(rmax0, __shfl_xor_sync(0xffffffffu, rmax0, 1));
        rmax0 = fmaxf(rmax0, __shfl_xor_sync(0xffffffffu, rmax0, 2));
        rmax1 = fmaxf(rmax1, __shfl_xor_sync(0xffffffffu, rmax1, 1));
        rmax1 = fmaxf(rmax1, __shfl_xor_sync(0xffffffffu, rmax1, 2));

        const float mn0 = fmaxf(m0, rmax0);
        const float mn1 = fmaxf(m1, rmax1);
        const float corr0 = __expf(m0 - mn0);
        const float corr1 = __expf(m1 - mn1);

        float rs0 = 0.f, rs1 = 0.f;
        uint32_t pf[8][4];
#pragma unroll
        for (int ni = 0; ni < 8; ++ni) {
            float p0 = __expf(sc[ni][0] - mn0);
            float p1 = __expf(sc[ni][1] - mn0);
            float p2 = __expf(sc[ni][2] - mn1);
            float p3 = __expf(sc[ni][3] - mn1);
            rs0 += p0 + p1;
            rs1 += p2 + p3;
            pf[ni][0] = f2tf32(p0);
            pf[ni][1] = f2tf32(p2);
            pf[ni][2] = f2tf32(p1);
            pf[ni][3] = f2tf32(p3);
        }
        rs0 += __shfl_xor_sync(0xffffffffu, rs0, 1);
        rs0 += __shfl_xor_sync(0xffffffffu, rs0, 2);
        rs1 += __shfl_xor_sync(0xffffffffu, rs1, 1);
        rs1 += __shfl_xor_sync(0xffffffffu, rs1, 2);

        l0 = l0 * corr0 + rs0;
        l1 = l1 * corr1 + rs1;
        m0 = mn0; m1 = mn1;

#pragma unroll
        for (int di = 0; di < 8; ++di) {
            oacc[di][0] *= corr0; oacc[di][1] *= corr0;
            oacc[di][2] *= corr1; oacc[di][3] *= corr1;
        }

#pragma unroll
        for (int di = 0; di < 8; ++di) {
#pragma unroll
            for (int ks = 0; ks < 8; ++ks) {
                uint32_t bf[2];
                bf[0] = Vs[ks * 8 + qq * 2][di * 8 + gr];
                bf[1] = Vs[ks * 8 + qq * 2 + 1][di * 8 + gr];
                mma_tf32(oacc[di], pf[ks], bf);
            }
        }
    }

    const float inv0 = 1.f / l0;
    const float inv1 = 1.f / l1;
    const size_t row0 = (size_t)(b * S_ + q0 + warp * 16 + gr);
#pragma unroll
    for (int di = 0; di < 8; ++di) {
        const int col = h * HD_ + di * 8 + qq * 2;
        *(float2*)&O[row0 * D_ + col] =
            make_float2(oacc[di][0] * inv0, oacc[di][1] * inv0);
        *(float2*)&O[(row0 + 8) * D_ + col] =
            make_float2(oacc[di][2] * inv1, oacc[di][3] * inv1);
    }
}

// ---------------------------------------------------------------------------
// out = LayerNorm(A_row + B_row) * g + beta ;  row length 768, 256 threads.
// ---------------------------------------------------------------------------
__global__ void __launch_bounds__(256)
add_ln_kernel(const float* __restrict__ A, const float* __restrict__ Bm,
              const float* __restrict__ g, const float* __restrict__ beta,
              float* __restrict__ out)
{
    const int row = blockIdx.x;
    const int tid = threadIdx.x;
    const float* a = A  + (size_t)row * D_;
    const float* b = Bm + (size_t)row * D_;

    float v[3], s = 0.f, ss = 0.f;
#pragma unroll
    for (int i = 0; i < 3; ++i) {
        int c = tid + i * 256;
        v[i] = a[c] + b[c];
        s  += v[i];
        ss += v[i] * v[i];
    }
#pragma unroll
    for (int o = 16; o > 0; o >>= 1) {
        s  += __shfl_xor_sync(0xffffffffu, s,  o);
        ss += __shfl_xor_sync(0xffffffffu, ss, o);
    }
    __shared__ float shs[8], shss[8];
    if ((tid & 31) == 0) { shs[tid >> 5] = s; shss[tid >> 5] = ss; }
    __syncthreads();
    __shared__ float sh_mean, sh_inv;
    if (tid == 0) {
        float ts = 0.f, tss = 0.f;
#pragma unroll
        for (int w = 0; w < 8; ++w) { ts += shs[w]; tss += shss[w]; }
        float mean = ts * (1.f / D_);
        float var  = tss * (1.f / D_) - mean * mean;
        sh_mean = mean;
        sh_inv  = rsqrtf(var + 1e-5f);
    }
    __syncthreads();
    const float mean = sh_mean, inv = sh_inv;
    float* o = out + (size_t)row * D_;
#pragma unroll
    for (int i = 0; i < 3; ++i) {
        int c = tid + i * 256;
        o[c] = (v[i] - mean) * inv * g[c] + beta[c];
    }
}

// ---------------------------------------------------------------------------
static void* sym_addr(const void* symbol) {
    void* p = nullptr;
    cudaGetSymbolAddress(&p, symbol);
    return p;
}

extern "C" void kernel_launch(void* const* d_in, const int* in_sizes, int n_in,
                              void* d_out, int out_size)
{
    const float* x     = (const float*)d_in[0];
    // d_in[1] = mask (unused: causal handled analytically)
    const float* alibi = (const float*)d_in[2];
    const float* wq = (const float*)d_in[3];
    const float* bq = (const float*)d_in[4];
    const float* wk = (const float*)d_in[5];
    const float* bk = (const float*)d_in[6];
    const float* wv = (const float*)d_in[7];
    const float* bv = (const float*)d_in[8];
    const float* wo = (const float*)d_in[9];
    const float* bo = (const float*)d_in[10];
    const float* w1 = (const float*)d_in[11];
    const float* b1 = (const float*)d_in[12];
    const float* w2 = (const float*)d_in[13];
    const float* b2 = (const float*)d_in[14];
    const float* g1 = (const float*)d_in[15];
    const float* be1= (const float*)d_in[16];
    const float* g2 = (const float*)d_in[17];
    const float* be2= (const float*)d_in[18];
    float* out = (float*)d_out;

    float* q   = (float*)sym_addr(gQ);
    float* k   = (float*)sym_addr(gK);
    float* v   = (float*)sym_addr(gV);
    float* ctx = (float*)sym_addr(gCtx);
    float* tmp = (float*)sym_addr(gTmp);
    float* x1  = (float*)sym_addr(gX1);
    float* ff  = (float*)sym_addr(gFF);

    cudaFuncSetAttribute(attn_tc_kernel,
                         cudaFuncAttributeMaxDynamicSharedMemorySize,
                         ATTN_SMEM_BYTES);
    cudaFuncSetAttribute(gemm_v3_qkv,
                         cudaFuncAttributeMaxDynamicSharedMemorySize,
                         GEMM_SMEM_BYTES);
    cudaFuncSetAttribute(gemm_v3<0>,
                         cudaFuncAttributeMaxDynamicSharedMemorySize,
                         GEMM_SMEM_BYTES);
    cudaFuncSetAttribute(gemm_v3<1>,
                         cudaFuncAttributeMaxDynamicSharedMemorySize,
                         GEMM_SMEM_BYTES);

    // QKV projections fused into one launch (grid.z = 3)
    dim3 gqkv(D_ / 128, ROWS / 128, 3);
    gemm_v3_qkv<<<gqkv, 128, GEMM_SMEM_BYTES>>>(x, wq, bq, wk, bk, wv, bv, q, k, v);

    // attention (tf32 tensor cores, fp32 softmax)
    dim3 gattn(S_ / 64, B_ * H_);
    attn_tc_kernel<<<gattn, 128, ATTN_SMEM_BYTES>>>(q, k, v, alibi, ctx);

    // output projection, residual + LN1
    dim3 gproj(D_ / 128, ROWS / 128);
    gemm_v3<0><<<gproj, 128, GEMM_SMEM_BYTES>>>(ctx, wo, bo, tmp, D_, D_);
    add_ln_kernel<<<ROWS, 256>>>(x, tmp, g1, be1, x1);

    // FFN
    dim3 gff1(FF_ / 128, ROWS / 128);
    gemm_v3<1><<<gff1, 128, GEMM_SMEM_BYTES>>>(x1, w1, b1, ff, FF_, D_);
    gemm_v3<0><<<gproj, 128, GEMM_SMEM_BYTES>>>(ff, w2, b2, tmp, D_, FF_);

    // residual + LN2 -> output
    add_ln_kernel<<<ROWS, 256>>>(x1, tmp, g2, be2, out);
}